// round 1
// baseline (speedup 1.0000x reference)
#include <cuda_runtime.h>

// TVConv: per-pixel spatially-varying 3x3 depthwise conv.
// x:           (B=8, C=96, H=128, W=128) f32
// weight_maps: (1, C=96, 3, 3, H=128, W=128) f32
// out:         (B=8, C=96, H=128, W=128) f32
//
// Strategy: one CTA = one channel c x 8-row strip. Each thread owns 4 output
// pixels (same w, rows stride-2) and holds their 36 weights in registers,
// loaded ONCE. Then loop b=0..7: cooperatively stage the 10x130 halo tile of
// x into shared, FMA, store. Weights hit DRAM exactly once (56.6 MB), x ~1.25x
// (63 MB), out once (50 MB) => ~170 MB total, memory-roofline bound.

#define BB 8
#define CC 96
#define HH 128
#define WW 128
#define TH 8          // output rows per block
#define RPT 4         // rows per thread (2 ty slots * 4 = 8 rows)
#define SPITCH 132    // shared row pitch (130 used + pad)

__global__ __launch_bounds__(256, 4)
void tvconv_kernel(const float* __restrict__ x,
                   const float* __restrict__ wm,
                   float* __restrict__ out) {
    const int c  = blockIdx.y;
    const int h0 = blockIdx.x * TH;
    const int tid = threadIdx.x;
    const int tw = tid & (WW - 1);   // 0..127 -> w
    const int ty = tid >> 7;         // 0..1

    __shared__ float sx[(TH + 2) * SPITCH];

    const int plane = HH * WW;       // 16384
    const float* wmc = wm + c * 9 * plane;

    // ---- load 4x9 weights into registers (coalesced per tap) ----
    float wreg[RPT][9];
    #pragma unroll
    for (int r = 0; r < RPT; r++) {
        const int h = h0 + ty + 2 * r;
        const int base = h * WW + tw;
        #pragma unroll
        for (int t = 0; t < 9; t++) {
            wreg[r][t] = __ldg(&wmc[t * plane + base]);
        }
    }

    const int cplane = c * plane;

    for (int b = 0; b < BB; b++) {
        const float* xb = x + (b * CC) * plane + cplane;

        // ---- stage (TH+2) x 130 halo tile into shared, zero-padded ----
        #pragma unroll
        for (int i = 0; i < 6; i++) {              // 6*256 = 1536 >= 1300
            int idx = tid + i * 256;
            if (idx < (TH + 2) * 130) {
                int row = idx / 130;
                int col = idx - row * 130;
                int gh = h0 - 1 + row;
                int gw = col - 1;
                float v = 0.0f;
                if (gh >= 0 && gh < HH && (unsigned)gw < (unsigned)WW)
                    v = __ldg(&xb[gh * WW + gw]);
                sx[row * SPITCH + col] = v;
            }
        }
        __syncthreads();

        float* ob = out + (b * CC) * plane + cplane;
        #pragma unroll
        for (int r = 0; r < RPT; r++) {
            const int lr = ty + 2 * r;             // local output row 0..7
            float acc = 0.0f;
            #pragma unroll
            for (int kh = 0; kh < 3; kh++) {
                const float* srow = &sx[(lr + kh) * SPITCH + tw];
                acc = fmaf(wreg[r][kh * 3 + 0], srow[0], acc);
                acc = fmaf(wreg[r][kh * 3 + 1], srow[1], acc);
                acc = fmaf(wreg[r][kh * 3 + 2], srow[2], acc);
            }
            ob[(h0 + lr) * WW + tw] = acc;
        }
        __syncthreads();   // protect sx before next batch's staging
    }
}

extern "C" void kernel_launch(void* const* d_in, const int* in_sizes, int n_in,
                              void* d_out, int out_size) {
    const float* x  = (const float*)d_in[0];
    const float* wm = (const float*)d_in[1];
    float* out = (float*)d_out;

    dim3 grid(HH / TH, CC);   // 16 x 96 = 1536 CTAs
    tvconv_kernel<<<grid, 256>>>(x, wm, out);
}

// round 2
// speedup vs baseline: 1.5927x; 1.5927x over previous
#include <cuda_runtime.h>

// TVConv: per-pixel spatially-varying 3x3 depthwise conv.
// x:           (B=8, C=96, H=128, W=128) f32
// weight_maps: (1, C=96, 3, 3, H=128, W=128) f32
// out:         (B=8, C=96, H=128, W=128) f32
//
// One CTA = (channel c, 8-row strip). Weights (36/thread) loaded once into
// registers, reused for all 8 batches. Per batch, the 10x128 interior of the
// halo tile is staged with 16B cp.async into a double buffer so batch b+1's
// DRAM latency overlaps batch b's compute. Halo COLUMNS are always zero
// (padding) -> written once. Halo ROWS out of range are zero-filled via the
// cp.async src-size=0 form.

#define BB 8
#define CC 96
#define HH 128
#define WW 128
#define TH 8          // output rows per block
#define RPT 4         // rows per thread (2 ty slots * 4 = 8)
#define SPITCH 136    // floats per shared row (4 pad + 1 halo + 128 + 1 halo + pad)
#define TROWS (TH + 2)

__device__ __forceinline__ void cp_async16(void* smem_dst, const void* gsrc, int src_bytes) {
    unsigned saddr = (unsigned)__cvta_generic_to_shared(smem_dst);
    asm volatile("cp.async.cg.shared.global [%0], [%1], 16, %2;\n"
                 :: "r"(saddr), "l"(gsrc), "r"(src_bytes));
}
__device__ __forceinline__ void cp_async_commit() {
    asm volatile("cp.async.commit_group;\n" ::: "memory");
}
template <int N>
__device__ __forceinline__ void cp_async_wait() {
    asm volatile("cp.async.wait_group %0;\n" :: "n"(N) : "memory");
}

__global__ __launch_bounds__(256, 4)
void tvconv_kernel(const float* __restrict__ x,
                   const float* __restrict__ wm,
                   float* __restrict__ out) {
    const int c   = blockIdx.y;
    const int h0  = blockIdx.x * TH;
    const int tid = threadIdx.x;
    const int tw  = tid & (WW - 1);   // 0..127 -> output w
    const int ty  = tid >> 7;         // 0..1

    __shared__ __align__(16) float sx[2][TROWS * SPITCH];

    const int plane = HH * WW;        // 16384
    const float* wmc = wm + c * 9 * plane;

    // ---- halo columns are permanently zero (x pad) ----
    if (tid < 2 * TROWS) {
        int buf = tid >> 1;           // reuse: tid<20 covers both cols of buf.. map explicitly
    }
    // explicit: 40 zero writes (2 bufs x 10 rows x 2 cols)
    if (tid < 40) {
        int b   = tid >> 5;                 // crude split; do exact below
    }
    {
        // 2 bufs * TROWS rows * 2 cols = 40 entries
        if (tid < 2 * TROWS * 2) {
            int e   = tid;
            int buf = e & 1;
            int r   = (e >> 1) % TROWS;
            int sid = (e >> 1) / TROWS;     // 0 -> left col, 1 -> right col
            sx[buf][r * SPITCH + (sid == 0 ? 3 : 132)] = 0.0f;
        }
    }

    // ---- load 4x9 weights into registers (coalesced per tap) ----
    float wreg[RPT][9];
    #pragma unroll
    for (int r = 0; r < RPT; r++) {
        const int h = h0 + ty + 2 * r;
        const int base = h * WW + tw;
        #pragma unroll
        for (int t = 0; t < 9; t++) {
            wreg[r][t] = __ldg(&wmc[t * plane + base]);
        }
    }

    const int cplane = c * plane;

    // staging role: 320 float4 ops per tile. tid 0..255 -> rows 0..7,
    // tid 0..63 also -> rows 8..9.
    const int k0   = tid & 31;        // float4 index within row
    const int row0 = tid >> 5;        // 0..7
    const int row1 = 8 + (tid >> 5);  // valid only for tid < 64

    auto stage = [&](int buf, int b) {
        const float* xb = x + (b * CC) * plane + cplane;
        {
            int gh = h0 - 1 + row0;
            int ok = (gh >= 0 && gh < HH);
            int ghc = ok ? gh : 0;
            cp_async16(&sx[buf][row0 * SPITCH + 4 + 4 * k0],
                       xb + ghc * WW + 4 * k0, ok ? 16 : 0);
        }
        if (tid < 64) {
            int gh = h0 - 1 + row1;
            int ok = (gh >= 0 && gh < HH);
            int ghc = ok ? gh : 0;
            cp_async16(&sx[buf][row1 * SPITCH + 4 + 4 * k0],
                       xb + ghc * WW + 4 * k0, ok ? 16 : 0);
        }
        cp_async_commit();
    };

    // preload batch 0
    stage(0, 0);

    for (int b = 0; b < BB; b++) {
        const int p = b & 1;
        if (b + 1 < BB) {
            stage(p ^ 1, b + 1);
            cp_async_wait<1>();       // buf p complete; b+1 still in flight
        } else {
            cp_async_wait<0>();
        }
        __syncthreads();

        float* ob = out + (b * CC) * plane + cplane;
        #pragma unroll
        for (int r = 0; r < RPT; r++) {
            const int lr = ty + 2 * r;            // local output row 0..7
            float acc = 0.0f;
            #pragma unroll
            for (int kh = 0; kh < 3; kh++) {
                const float* srow = &sx[p][(lr + kh) * SPITCH + tw + 3];
                acc = fmaf(wreg[r][kh * 3 + 0], srow[0], acc);
                acc = fmaf(wreg[r][kh * 3 + 1], srow[1], acc);
                acc = fmaf(wreg[r][kh * 3 + 2], srow[2], acc);
            }
            ob[(h0 + lr) * WW + tw] = acc;
        }
        __syncthreads();   // buf p may be refilled at iter b+1's stage
    }
}

extern "C" void kernel_launch(void* const* d_in, const int* in_sizes, int n_in,
                              void* d_out, int out_size) {
    const float* x  = (const float*)d_in[0];
    const float* wm = (const float*)d_in[1];
    float* out = (float*)d_out;

    dim3 grid(HH / TH, CC);   // 16 x 96 = 1536 CTAs
    tvconv_kernel<<<grid, 256>>>(x, wm, out);
}